// round 7
// baseline (speedup 1.0000x reference)
#include <cuda_runtime.h>
#include <cuda_fp16.h>
#include <cstdint>

#define F_IN 116
#define K2N  58          // F_IN/2
#define H 8
#define C 32
#define HC 256           // H*C
#define MAXN 50016
#define MAXE 1000000     // >= E + 3N + pad
#define NEG_SLOPE 0.2f
#define ROWS 32          // gemm rows per block
#define XSP 120          // padded shared row (16B multiple)
#define SCHUNK 2048      // scan chunk per block

// ---------------- device scratch (no allocations allowed) ----------------
__device__ __align__(16) __half g_xt_h[(size_t)MAXN * HC]; // fp16 features; row N stays 0 (sentinel)
__device__ __align__(16) float g_as[(size_t)MAXN * H];     // alpha_src (row N = -inf sentinel)
__device__ __align__(16) float g_ad[(size_t)MAXN * H];     // alpha_dst
__device__ unsigned long long g_Wt[K2N * HC];              // W repacked into k-pairs (f32x2)
__device__ __align__(16) int g_deg[MAXN];                  // zeroed by tail of agg (self-restoring)
__device__ int g_off[MAXN + 1];                            // aligned (ceil4) offsets
__device__ int g_cur[MAXN];
__device__ __align__(16) int g_csr[MAXE];                  // src ids grouped by dst, sentinel-padded
__device__ int g_idx64;

// ---------------- side stream + events, created once at program start ----------------
struct HxStreams {
    cudaStream_t s2;
    cudaEvent_t evFork, evJoin;
    HxStreams() {
        cudaStreamCreateWithFlags(&s2, cudaStreamNonBlocking);
        cudaEventCreateWithFlags(&evFork, cudaEventDisableTiming);
        cudaEventCreateWithFlags(&evJoin, cudaEventDisableTiming);
    }
};
static HxStreams g_hx;

// ---------------- fused init: detect + csr prefill + W repack + sentinel + COUNT ----------------
// g_deg must be zero on entry: static-zero on first call, re-zeroed by agg tail thereafter.
__global__ void init_count_kernel(const int* ei32, const void* __restrict__ ei,
                                  int n_check, const float* __restrict__ W,
                                  int N, int E, int EP) {
    __shared__ int s_is64;
    if (threadIdx.x == 0) {
        int is64 = 1;
        for (int k = 0; k < n_check; k++)
            if (ei32[2 * k + 1] != 0) { is64 = 0; break; }
        s_is64 = is64;
        if (blockIdx.x == 0) g_idx64 = is64;
    }
    __syncthreads();
    int i = blockIdx.x * blockDim.x + threadIdx.x;

    if (i < EP) g_csr[i] = N;                    // sentinel prefill
    if (i < K2N * HC) {
        int k2 = i / HC, j = i - k2 * HC;
        unsigned int lo = __float_as_uint(W[(2 * k2) * HC + j]);
        unsigned int hi = __float_as_uint(W[(2 * k2 + 1) * HC + j]);
        g_Wt[i] = ((unsigned long long)hi << 32) | lo;
    }
    if (i < H) g_as[(size_t)N * H + i] = __int_as_float(0xff800000);  // -inf sentinel row

    if (i < E) {
        int dst;
        if (s_is64) dst = (int)((const long long*)ei)[(size_t)E + i];
        else        dst = ((const int*)ei)[E + i];
        atomicAdd(&g_deg[dst], 1);
    }
}

// ---------------- single-kernel exclusive scan of ceil4(deg) -> g_off, g_cur ----------------
// Each block redundantly sums all degrees before its chunk (cheap: <=200KB L2 reads/block).
__device__ __forceinline__ int ceil4(int v) { return (v + 3) & ~3; }

__global__ void scan_kernel(int N) {
    __shared__ int sm[256];
    int b0 = blockIdx.x * SCHUNK;                // multiple of 2048 -> int4-aligned
    int t = threadIdx.x;

    // base = sum of ceil4(deg[0..b0)) via vectorized grid of 256 threads
    int base_p = 0;
    for (int i = t * 4; i < b0; i += 1024) {
        int4 d = *(const int4*)&g_deg[i];
        base_p += ceil4(d.x) + ceil4(d.y) + ceil4(d.z) + ceil4(d.w);
    }
    sm[t] = base_p;
    __syncthreads();
    for (int o = 128; o > 0; o >>= 1) {
        if (t < o) sm[t] += sm[t + o];
        __syncthreads();
    }
    int base = sm[0];
    __syncthreads();

    // local scan over own chunk (8 contiguous per thread)
    const int PT = SCHUNK / 256;
    int cbase = b0 + t * PT;
    int loc[PT];
    int s = 0;
#pragma unroll
    for (int k = 0; k < PT; k++) {
        int i = cbase + k;
        loc[k] = s;
        if (i < N) s += ceil4(g_deg[i]);
    }
    sm[t] = s;
    __syncthreads();
    for (int o = 1; o < 256; o <<= 1) {
        int v = (t >= o) ? sm[t - o] : 0;
        __syncthreads();
        sm[t] += v;
        __syncthreads();
    }
    int tbase = base + ((t > 0) ? sm[t - 1] : 0);
#pragma unroll
    for (int k = 0; k < PT; k++) {
        int i = cbase + k;
        if (i < N) {
            int o = tbase + loc[k];
            g_off[i] = o;
            g_cur[i] = o;
        }
    }
    if (blockIdx.x == gridDim.x - 1 && t == 255) g_off[N] = base + sm[255];
}

// ---------------- scatter src ids into CSR slots (decode edges directly) ----------------
__global__ void scatter_kernel(const void* __restrict__ ei, int E) {
    int i = blockIdx.x * blockDim.x + threadIdx.x;
    if (i >= E) return;
    int src, dst;
    if (g_idx64) {
        const long long* p = (const long long*)ei;
        src = (int)p[i];
        dst = (int)p[(size_t)E + i];
    } else {
        const int* p = (const int*)ei;
        src = p[i];
        dst = p[E + i];
    }
    int pos = atomicAdd(&g_cur[dst], 1);
    g_csr[pos] = src;
}

// ---------------- xt = x @ W (f32x2 FFMA2, LDS.128) + alpha_src/alpha_dst ----------------
__global__ void __launch_bounds__(256, 2)
gemm_alpha_kernel(const float* __restrict__ x,
                  const float* __restrict__ att_src,
                  const float* __restrict__ att_dst,
                  int N) {
    __shared__ __align__(16) float xs[ROWS][XSP];
    int row0 = blockIdx.x * ROWS;

    for (int i = threadIdx.x; i < ROWS * F_IN; i += 256) {
        int r = i / F_IN, k = i - r * F_IN;
        int gr = row0 + r;
        xs[r][k] = (gr < N) ? x[(size_t)gr * F_IN + k] : 0.0f;
    }
    __syncthreads();

    int j = threadIdx.x;
    unsigned long long acc[ROWS];
#pragma unroll
    for (int r = 0; r < ROWS; r++) acc[r] = 0ull;

    const unsigned long long* wt = g_Wt + j;
    for (int k4 = 0; k4 < K2N / 2; k4++) {
        unsigned long long w0 = wt[(2 * k4) * HC];
        unsigned long long w1 = wt[(2 * k4 + 1) * HC];
#pragma unroll
        for (int r = 0; r < ROWS; r++) {
            ulonglong2 a2 = *(const ulonglong2*)&xs[r][4 * k4];
            asm("fma.rn.f32x2 %0, %1, %2, %0;" : "+l"(acc[r]) : "l"(a2.x), "l"(w0));
            asm("fma.rn.f32x2 %0, %1, %2, %0;" : "+l"(acc[r]) : "l"(a2.y), "l"(w1));
        }
    }

    float asv = att_src[j];
    float adv = att_dst[j];
    int h = j >> 5;

#pragma unroll
    for (int r = 0; r < ROWS; r++) {
        float lo, hi;
        asm("mov.b64 {%0, %1}, %2;" : "=f"(lo), "=f"(hi) : "l"(acc[r]));
        float v = lo + hi;
        int gr = row0 + r;
        if (gr < N) g_xt_h[(size_t)gr * HC + j] = __float2half_rn(v);
        float ps = v * asv;
        float pd = v * adv;
#pragma unroll
        for (int o = 16; o > 0; o >>= 1) {
            ps += __shfl_xor_sync(0xffffffffu, ps, o);
            pd += __shfl_xor_sync(0xffffffffu, pd, o);
        }
        if ((j & 31) == 0 && gr < N) {
            g_as[(size_t)gr * H + h] = ps;
            g_ad[(size_t)gr * H + h] = pd;
        }
    }
}

// ---------------- fused gather-aggregate + softmax + head-mean + bias + relu ----------------
__device__ __forceinline__ void acc_row(const float4& raw, float ev, float* acc) {
    const __half2* hp = (const __half2*)&raw;
    float2 f0 = __half22float2(hp[0]);
    float2 f1 = __half22float2(hp[1]);
    float2 f2 = __half22float2(hp[2]);
    float2 f3 = __half22float2(hp[3]);
    acc[0] = fmaf(ev, f0.x, acc[0]); acc[1] = fmaf(ev, f0.y, acc[1]);
    acc[2] = fmaf(ev, f1.x, acc[2]); acc[3] = fmaf(ev, f1.y, acc[3]);
    acc[4] = fmaf(ev, f2.x, acc[4]); acc[5] = fmaf(ev, f2.y, acc[5]);
    acc[6] = fmaf(ev, f3.x, acc[6]); acc[7] = fmaf(ev, f3.y, acc[7]);
}

__global__ void agg_kernel(const float* __restrict__ bias,
                           float* __restrict__ out, int N) {
    int gw = (blockIdx.x * blockDim.x + threadIdx.x) >> 5;
    int lane = threadIdx.x & 31;
    if (gw >= N) return;
    int n = gw;
    int h = lane >> 2;

    if (lane == 0) g_deg[n] = 0;    // restore for next graph replay (init_count expects zeros)

    float ad_h = g_ad[(size_t)n * H + h];

    // self loop
    float a = g_as[(size_t)n * H + h] + ad_h;
    a = (a > 0.0f) ? a : NEG_SLOPE * a;
    float e = __expf(a);
    float s = e;

    float acc[8] = {0, 0, 0, 0, 0, 0, 0, 0};
    {
        float4 raw = __ldcv(((const float4*)(g_xt_h + (size_t)n * HC)) + lane);
        acc_row(raw, e, acc);
    }

    int beg = g_off[n];
    int end = g_off[n + 1];     // ceil4-aligned; padding = sentinel entries (exp=0, zero row)
    for (int p = beg; p < end; p += 4) {
        int4 sv = *(const int4*)(g_csr + p);
        float a0 = g_as[(size_t)sv.x * H + h] + ad_h;
        float a1 = g_as[(size_t)sv.y * H + h] + ad_h;
        float a2 = g_as[(size_t)sv.z * H + h] + ad_h;
        float a3 = g_as[(size_t)sv.w * H + h] + ad_h;
        a0 = (a0 > 0.0f) ? a0 : NEG_SLOPE * a0;
        a1 = (a1 > 0.0f) ? a1 : NEG_SLOPE * a1;
        a2 = (a2 > 0.0f) ? a2 : NEG_SLOPE * a2;
        a3 = (a3 > 0.0f) ? a3 : NEG_SLOPE * a3;
        float e0 = __expf(a0);
        float e1 = __expf(a1);
        float e2 = __expf(a2);
        float e3 = __expf(a3);
        s += (e0 + e1) + (e2 + e3);
        float4 r0 = __ldcv(((const float4*)(g_xt_h + (size_t)sv.x * HC)) + lane);
        float4 r1 = __ldcv(((const float4*)(g_xt_h + (size_t)sv.y * HC)) + lane);
        float4 r2 = __ldcv(((const float4*)(g_xt_h + (size_t)sv.z * HC)) + lane);
        float4 r3 = __ldcv(((const float4*)(g_xt_h + (size_t)sv.w * HC)) + lane);
        acc_row(r0, e0, acc);
        acc_row(r1, e1, acc);
        acc_row(r2, e2, acc);
        acc_row(r3, e3, acc);
    }

    float inv = 1.0f / (s + 1e-16f);
    float r[8];
#pragma unroll
    for (int i = 0; i < 8; i++) r[i] = acc[i] * inv;

    // sum over heads: butterfly across lanes differing in bits 2..4 (same lane&3)
#pragma unroll
    for (int i = 0; i < 8; i++) {
        r[i] += __shfl_xor_sync(0xffffffffu, r[i], 4);
        r[i] += __shfl_xor_sync(0xffffffffu, r[i], 8);
        r[i] += __shfl_xor_sync(0xffffffffu, r[i], 16);
    }

    if (lane < 4) {
        float o[8];
#pragma unroll
        for (int i = 0; i < 8; i++) {
            float v = r[i] * 0.125f + bias[lane * 8 + i];
            o[i] = (v > 0.0f) ? v : 0.0f;
        }
        float4* orow = (float4*)(out + (size_t)n * C + lane * 8);
        orow[0] = make_float4(o[0], o[1], o[2], o[3]);
        orow[1] = make_float4(o[4], o[5], o[6], o[7]);
    }
}

// ---------------- launch: 5 kernels, fork-join — CSR build || GEMM ----------------
extern "C" void kernel_launch(void* const* d_in, const int* in_sizes, int n_in,
                              void* d_out, int out_size) {
    const float* x       = (const float*)d_in[0];
    const void*  ei      = d_in[1];
    const float* W       = (const float*)d_in[2];
    const float* att_src = (const float*)d_in[3];
    const float* att_dst = (const float*)d_in[4];
    const float* bias    = (const float*)d_in[5];

    int N = in_sizes[0] / F_IN;
    int E = in_sizes[1] / 2;
    int n_check = E > 64 ? 64 : E;

    int EP = E + 3 * N + 64;
    if (EP > MAXE) EP = MAXE;
    int initT = EP;
    if (E > initT) initT = E;
    if (K2N * HC > initT) initT = K2N * HC;
    if (N + 1 > initT) initT = N + 1;

    // (1) fused init+count
    init_count_kernel<<<(initT + 255) / 256, 256>>>((const int*)ei, ei, n_check, W, N, E, EP);

    // (2) gemm on side stream (needs g_Wt from init)
    cudaEventRecord(g_hx.evFork, 0);
    cudaStreamWaitEvent(g_hx.s2, g_hx.evFork, 0);
    gemm_alpha_kernel<<<(N + ROWS - 1) / ROWS, 256, 0, g_hx.s2>>>(x, att_src, att_dst, N);
    cudaEventRecord(g_hx.evJoin, g_hx.s2);

    // (3) fused scan, (4) scatter  [main stream]
    int NB = (N + SCHUNK - 1) / SCHUNK;
    scan_kernel<<<NB, 256>>>(N);
    scatter_kernel<<<(E + 255) / 256, 256>>>(ei, E);

    // (5) aggregate (joins gemm)
    cudaStreamWaitEvent(0, g_hx.evJoin, 0);
    agg_kernel<<<(N + 7) / 8, 256>>>(bias, (float*)d_out, N);
}

// round 8
// speedup vs baseline: 1.0883x; 1.0883x over previous
#include <cuda_runtime.h>
#include <cuda_fp16.h>
#include <math_constants.h>
#include <cstdint>

#define F_IN 116
#define K2N  58          // F_IN/2
#define H 8
#define C 32
#define HC 256           // H*C
#define MAXN 50016
#define MAXE 1000000     // >= E + 3N + pad
#define NEG_SLOPE 0.2f
#define ROWS 32          // gemm rows per block
#define XSP 120          // padded shared row (16B multiple)
#define SCHUNK 2048      // scan chunk per block

// ---------------- device scratch (no allocations allowed) ----------------
__device__ __align__(16) __half g_xt_h[(size_t)MAXN * HC]; // fp16 features; row N stays 0 (sentinel)
__device__ __align__(16) float g_as[(size_t)MAXN * H];     // alpha_src (row N = -inf sentinel)
__device__ __align__(16) float g_ad[(size_t)MAXN * H];     // alpha_dst
__device__ unsigned long long g_Wt[K2N * HC];              // W repacked into k-pairs (f32x2)
__device__ __align__(16) int g_deg[MAXN];
__device__ int g_off[MAXN + 1];                            // aligned (ceil4) offsets
__device__ int g_cur[MAXN];
__device__ __align__(16) int g_csr[MAXE];                  // src ids grouped by dst, sentinel-padded
__device__ int g_idx64;

// ---------------- side stream + events, created once at program start ----------------
struct HxStreams {
    cudaStream_t s2;
    cudaEvent_t evFork, evJoin;
    HxStreams() {
        cudaStreamCreateWithFlags(&s2, cudaStreamNonBlocking);
        cudaEventCreateWithFlags(&evFork, cudaEventDisableTiming);
        cudaEventCreateWithFlags(&evJoin, cudaEventDisableTiming);
    }
};
static HxStreams g_hx;

// ---------------- init: detect + zero deg + sentinel + W repack + csr prefill ----------------
__global__ void init_kernel(const int* ei32, int n_check, const float* __restrict__ W,
                            int N, int EP) {
    int i = blockIdx.x * blockDim.x + threadIdx.x;
    if (i == 0) {
        int is64 = 1;
        for (int k = 0; k < n_check; k++)
            if (ei32[2 * k + 1] != 0) { is64 = 0; break; }
        g_idx64 = is64;
    }
    if (i < N) g_deg[i] = 0;
    if (i == N) {
#pragma unroll
        for (int h = 0; h < H; h++) g_as[(size_t)N * H + h] = -CUDART_INF_F;
    }
    if (i < K2N * HC) {
        int k2 = i / HC, j = i - k2 * HC;
        unsigned int lo = __float_as_uint(W[(2 * k2) * HC + j]);
        unsigned int hi = __float_as_uint(W[(2 * k2 + 1) * HC + j]);
        g_Wt[i] = ((unsigned long long)hi << 32) | lo;
    }
    if (i < EP) g_csr[i] = N;   // sentinel prefill
}

// ---------------- count in-degrees (dst half only) ----------------
__global__ void count_kernel(const void* __restrict__ ei, int E) {
    int i = blockIdx.x * blockDim.x + threadIdx.x;
    if (i >= E) return;
    int dst;
    if (g_idx64) dst = (int)((const long long*)ei)[(size_t)E + i];
    else         dst = ((const int*)ei)[E + i];
    atomicAdd(&g_deg[dst], 1);
}

// ---------------- single-kernel exclusive scan of ceil4(deg) -> g_off, g_cur ----------------
// Each block redundantly sums all degrees before its chunk (<=200KB L2 reads/block).
__device__ __forceinline__ int ceil4(int v) { return (v + 3) & ~3; }

__global__ void scan_kernel(int N) {
    __shared__ int sm[256];
    int b0 = blockIdx.x * SCHUNK;                // multiple of 2048 -> int4-aligned
    int t = threadIdx.x;

    int base_p = 0;
    for (int i = t * 4; i < b0; i += 1024) {
        int4 d = *(const int4*)&g_deg[i];
        base_p += ceil4(d.x) + ceil4(d.y) + ceil4(d.z) + ceil4(d.w);
    }
    sm[t] = base_p;
    __syncthreads();
    for (int o = 128; o > 0; o >>= 1) {
        if (t < o) sm[t] += sm[t + o];
        __syncthreads();
    }
    int base = sm[0];
    __syncthreads();

    const int PT = SCHUNK / 256;
    int cbase = b0 + t * PT;
    int loc[PT];
    int s = 0;
#pragma unroll
    for (int k = 0; k < PT; k++) {
        int i = cbase + k;
        loc[k] = s;
        if (i < N) s += ceil4(g_deg[i]);
    }
    sm[t] = s;
    __syncthreads();
    for (int o = 1; o < 256; o <<= 1) {
        int v = (t >= o) ? sm[t - o] : 0;
        __syncthreads();
        sm[t] += v;
        __syncthreads();
    }
    int tbase = base + ((t > 0) ? sm[t - 1] : 0);
#pragma unroll
    for (int k = 0; k < PT; k++) {
        int i = cbase + k;
        if (i < N) {
            int o = tbase + loc[k];
            g_off[i] = o;
            g_cur[i] = o;
        }
    }
    if (blockIdx.x == gridDim.x - 1 && t == 255) g_off[N] = base + sm[255];
}

// ---------------- scatter src ids into CSR slots ----------------
__global__ void scatter_kernel(const void* __restrict__ ei, int E) {
    int i = blockIdx.x * blockDim.x + threadIdx.x;
    if (i >= E) return;
    int src, dst;
    if (g_idx64) {
        const long long* p = (const long long*)ei;
        src = (int)p[i];
        dst = (int)p[(size_t)E + i];
    } else {
        const int* p = (const int*)ei;
        src = p[i];
        dst = p[E + i];
    }
    int pos = atomicAdd(&g_cur[dst], 1);
    g_csr[pos] = src;
}

// ---------------- xt = x @ W (f32x2 FFMA2, LDS.128) + alpha_src/alpha_dst ----------------
__global__ void __launch_bounds__(256, 2)
gemm_alpha_kernel(const float* __restrict__ x,
                  const float* __restrict__ att_src,
                  const float* __restrict__ att_dst,
                  int N) {
    __shared__ __align__(16) float xs[ROWS][XSP];
    int row0 = blockIdx.x * ROWS;

    for (int i = threadIdx.x; i < ROWS * F_IN; i += 256) {
        int r = i / F_IN, k = i - r * F_IN;
        int gr = row0 + r;
        xs[r][k] = (gr < N) ? x[(size_t)gr * F_IN + k] : 0.0f;
    }
    __syncthreads();

    int j = threadIdx.x;
    unsigned long long acc[ROWS];
#pragma unroll
    for (int r = 0; r < ROWS; r++) acc[r] = 0ull;

    const unsigned long long* wt = g_Wt + j;
    for (int k4 = 0; k4 < K2N / 2; k4++) {
        unsigned long long w0 = wt[(2 * k4) * HC];
        unsigned long long w1 = wt[(2 * k4 + 1) * HC];
#pragma unroll
        for (int r = 0; r < ROWS; r++) {
            ulonglong2 a2 = *(const ulonglong2*)&xs[r][4 * k4];
            asm("fma.rn.f32x2 %0, %1, %2, %0;" : "+l"(acc[r]) : "l"(a2.x), "l"(w0));
            asm("fma.rn.f32x2 %0, %1, %2, %0;" : "+l"(acc[r]) : "l"(a2.y), "l"(w1));
        }
    }

    float asv = att_src[j];
    float adv = att_dst[j];
    int h = j >> 5;

#pragma unroll
    for (int r = 0; r < ROWS; r++) {
        float lo, hi;
        asm("mov.b64 {%0, %1}, %2;" : "=f"(lo), "=f"(hi) : "l"(acc[r]));
        float v = lo + hi;
        int gr = row0 + r;
        if (gr < N) g_xt_h[(size_t)gr * HC + j] = __float2half_rn(v);
        float ps = v * asv;
        float pd = v * adv;
#pragma unroll
        for (int o = 16; o > 0; o >>= 1) {
            ps += __shfl_xor_sync(0xffffffffu, ps, o);
            pd += __shfl_xor_sync(0xffffffffu, pd, o);
        }
        if ((j & 31) == 0 && gr < N) {
            g_as[(size_t)gr * H + h] = ps;
            g_ad[(size_t)gr * H + h] = pd;
        }
    }
}

// ---------------- fused gather-aggregate + softmax + head-mean + bias + relu ----------------
__device__ __forceinline__ void acc_row(const float4& raw, float ev, float* acc) {
    const __half2* hp = (const __half2*)&raw;
    float2 f0 = __half22float2(hp[0]);
    float2 f1 = __half22float2(hp[1]);
    float2 f2 = __half22float2(hp[2]);
    float2 f3 = __half22float2(hp[3]);
    acc[0] = fmaf(ev, f0.x, acc[0]); acc[1] = fmaf(ev, f0.y, acc[1]);
    acc[2] = fmaf(ev, f1.x, acc[2]); acc[3] = fmaf(ev, f1.y, acc[3]);
    acc[4] = fmaf(ev, f2.x, acc[4]); acc[5] = fmaf(ev, f2.y, acc[5]);
    acc[6] = fmaf(ev, f3.x, acc[6]); acc[7] = fmaf(ev, f3.y, acc[7]);
}

__global__ void agg_kernel(const float* __restrict__ bias,
                           float* __restrict__ out, int N) {
    int gw = (blockIdx.x * blockDim.x + threadIdx.x) >> 5;
    int lane = threadIdx.x & 31;
    if (gw >= N) return;
    int n = gw;
    int h = lane >> 2;

    float ad_h = g_ad[(size_t)n * H + h];

    // self loop
    float a = g_as[(size_t)n * H + h] + ad_h;
    a = (a > 0.0f) ? a : NEG_SLOPE * a;
    float e = __expf(a);
    float s = e;

    float acc[8] = {0, 0, 0, 0, 0, 0, 0, 0};
    {
        float4 raw = ((const float4*)(g_xt_h + (size_t)n * HC))[lane];
        acc_row(raw, e, acc);
    }

    int beg = g_off[n];
    int end = g_off[n + 1];     // ceil4-aligned; padding = sentinel entries (exp=0, zero row)
    for (int p = beg; p < end; p += 4) {
        int4 sv = *(const int4*)(g_csr + p);
        float a0 = g_as[(size_t)sv.x * H + h] + ad_h;
        float a1 = g_as[(size_t)sv.y * H + h] + ad_h;
        float a2 = g_as[(size_t)sv.z * H + h] + ad_h;
        float a3 = g_as[(size_t)sv.w * H + h] + ad_h;
        a0 = (a0 > 0.0f) ? a0 : NEG_SLOPE * a0;
        a1 = (a1 > 0.0f) ? a1 : NEG_SLOPE * a1;
        a2 = (a2 > 0.0f) ? a2 : NEG_SLOPE * a2;
        a3 = (a3 > 0.0f) ? a3 : NEG_SLOPE * a3;
        float e0 = __expf(a0);
        float e1 = __expf(a1);
        float e2 = __expf(a2);
        float e3 = __expf(a3);
        s += (e0 + e1) + (e2 + e3);
        float4 r0 = ((const float4*)(g_xt_h + (size_t)sv.x * HC))[lane];
        float4 r1 = ((const float4*)(g_xt_h + (size_t)sv.y * HC))[lane];
        float4 r2 = ((const float4*)(g_xt_h + (size_t)sv.z * HC))[lane];
        float4 r3 = ((const float4*)(g_xt_h + (size_t)sv.w * HC))[lane];
        acc_row(r0, e0, acc);
        acc_row(r1, e1, acc);
        acc_row(r2, e2, acc);
        acc_row(r3, e3, acc);
    }

    float inv = 1.0f / (s + 1e-16f);
    float r[8];
#pragma unroll
    for (int i = 0; i < 8; i++) r[i] = acc[i] * inv;

    // sum over heads: butterfly across lanes differing in bits 2..4 (same lane&3)
#pragma unroll
    for (int i = 0; i < 8; i++) {
        r[i] += __shfl_xor_sync(0xffffffffu, r[i], 4);
        r[i] += __shfl_xor_sync(0xffffffffu, r[i], 8);
        r[i] += __shfl_xor_sync(0xffffffffu, r[i], 16);
    }

    if (lane < 4) {
        float o[8];
#pragma unroll
        for (int i = 0; i < 8; i++) {
            float v = r[i] * 0.125f + bias[lane * 8 + i];
            o[i] = (v > 0.0f) ? v : 0.0f;
        }
        float4* orow = (float4*)(out + (size_t)n * C + lane * 8);
        orow[0] = make_float4(o[0], o[1], o[2], o[3]);
        orow[1] = make_float4(o[4], o[5], o[6], o[7]);
    }
}

// ---------------- launch: 6 kernels, fork-join — CSR build || GEMM ----------------
extern "C" void kernel_launch(void* const* d_in, const int* in_sizes, int n_in,
                              void* d_out, int out_size) {
    const float* x       = (const float*)d_in[0];
    const void*  ei      = d_in[1];
    const float* W       = (const float*)d_in[2];
    const float* att_src = (const float*)d_in[3];
    const float* att_dst = (const float*)d_in[4];
    const float* bias    = (const float*)d_in[5];

    int N = in_sizes[0] / F_IN;
    int E = in_sizes[1] / 2;
    int n_check = E > 64 ? 64 : E;

    int EP = E + 3 * N + 64;
    if (EP > MAXE) EP = MAXE;
    int initT = EP;
    if (K2N * HC > initT) initT = K2N * HC;
    if (N + 1 > initT) initT = N + 1;

    // (1) init
    init_kernel<<<(initT + 255) / 256, 256>>>((const int*)ei, n_check, W, N, EP);

    // (2) gemm on side stream — overlaps the CSR chain below
    cudaEventRecord(g_hx.evFork, 0);
    cudaStreamWaitEvent(g_hx.s2, g_hx.evFork, 0);
    gemm_alpha_kernel<<<(N + ROWS - 1) / ROWS, 256, 0, g_hx.s2>>>(x, att_src, att_dst, N);
    cudaEventRecord(g_hx.evJoin, g_hx.s2);

    // (3) count, (4) scan, (5) scatter  [main stream, concurrent with gemm]
    count_kernel<<<(E + 255) / 256, 256>>>(ei, E);
    int NB = (N + SCHUNK - 1) / SCHUNK;
    scan_kernel<<<NB, 256>>>(N);
    scatter_kernel<<<(E + 255) / 256, 256>>>(ei, E);

    // (6) aggregate (joins gemm)
    cudaStreamWaitEvent(0, g_hx.evJoin, 0);
    agg_kernel<<<(N + 7) / 8, 256>>>(bias, (float*)d_out, N);
}